// round 15
// baseline (speedup 1.0000x reference)
#include <cuda_runtime.h>
#include <cuda_fp16.h>
#include <cstdint>
#include <cstddef>

// Problem constants
#define BV 4
#define HN 16
#define SV 1024
#define DV 64
#define BH (BV*HN)

// fp16 k operand (device scratch; no allocation)
__device__ __half g_khi[(size_t)BH * SV * DV];
// per-slice epoch counters: g_scnt[bh*16+y] incremented exactly once per
// launch by CTA (bh,y) -> post-increment value == run epoch (replay-safe).
__device__ unsigned g_scnt[BH * 16];

__device__ __forceinline__ uint32_t smem_u32(const void* p) {
    uint32_t a;
    asm("{ .reg .u64 t; cvta.to.shared.u64 t, %1; cvt.u32.u64 %0, t; }" : "=r"(a) : "l"(p));
    return a;
}
__device__ __forceinline__ uint32_t sw128(uint32_t off) {
    return off ^ ((off >> 3) & 0x70);
}
__device__ __forceinline__ void ldsm_x4(uint32_t addr, uint32_t& r0, uint32_t& r1,
                                        uint32_t& r2, uint32_t& r3) {
    asm volatile("ldmatrix.sync.aligned.m8n8.x4.shared.b16 {%0,%1,%2,%3}, [%4];"
                 : "=r"(r0), "=r"(r1), "=r"(r2), "=r"(r3) : "r"(addr));
}
__device__ __forceinline__ void mma_f16(float* c, const uint32_t* a,
                                        uint32_t b0, uint32_t b1) {
    asm volatile(
        "mma.sync.aligned.m16n8k16.row.col.f32.f16.f16.f32 "
        "{%0,%1,%2,%3}, {%4,%5,%6,%7}, {%8,%9}, {%0,%1,%2,%3};"
        : "+f"(c[0]), "+f"(c[1]), "+f"(c[2]), "+f"(c[3])
        : "r"(a[0]), "r"(a[1]), "r"(a[2]), "r"(a[3]), "r"(b0), "r"(b1));
}
__device__ __forceinline__ void cp_async16(uint32_t smem_dst, const void* gsrc) {
    asm volatile("cp.async.cg.shared.global [%0], [%1], 16;"
                 :: "r"(smem_dst), "l"(gsrc));
}
#define CP_COMMIT() asm volatile("cp.async.commit_group;" ::: "memory")
#define CP_WAIT0()  asm volatile("cp.async.wait_group 0;"  ::: "memory")

// ---------------------------------------------------------------------------
// Single fused kernel: k-slice convert + per-slice epoch flags + fold
// prologue (overlapped with B0 prefetch) + persistent 64-row strip GEMM.
// grid (1, 16, 64) = 1024 CTAs, 128 threads, 4 CTAs/SM.
// SMEM overlays (from 1K-aligned base, 48K total):
//   fold:   Qh[0,8K) Ql[8K,16K) Mh[16K,24K) Ml[24K,32K)  B0[32K,48K)
//   j-loop: B1[0,16K)           A [16K,24K) (overlays Mh) B0[32K,48K)
// ---------------------------------------------------------------------------
#define OFF_QH 0
#define OFF_QL 8192
#define OFF_MH 16384
#define OFF_ML 24576
#define OFF_A  16384
#define OFF_B0 32768
#define OFF_B1 0
#define SC_SMEM (49152 + 1024)

__global__ __launch_bounds__(128, 4)
void score_mma_kernel(const float* __restrict__ q,
                      const float* __restrict__ kf,
                      const float* __restrict__ W,
                      const float* __restrict__ b,
                      const float* __restrict__ Wd,
                      float* __restrict__ out)
{
    extern __shared__ char smem_raw[];
    const uint32_t smem_base = smem_u32(smem_raw);
    const uint32_t base_al   = (smem_base + 1023u) & ~1023u;
    char* tilec = smem_raw + (base_al - smem_base);

    const int t    = threadIdx.x;
    const int wid  = t >> 5;
    const int lane = t & 31;
    const int bh   = blockIdx.z;
    const int h    = bh % HN;
    const int i0   = blockIdx.y * 64;

    const size_t boff = (size_t)bh * SV * DV;
    const __half* kh = g_khi + boff;

    // ================= K-SLICE CONVERT (own 64 rows) =================
    {
        const float* ks = kf + boff + (size_t)i0 * DV;
        __half2* kd = reinterpret_cast<__half2*>(g_khi + boff + (size_t)i0 * DV);
        #pragma unroll
        for (int it = 0; it < 8; it++) {
            const int idx = t + it * 128;
            float4 v = reinterpret_cast<const float4*>(ks)[idx];
            kd[2 * idx]     = __floats2half2_rn(v.x, v.y);
            kd[2 * idx + 1] = __floats2half2_rn(v.z, v.w);
        }
    }
    __threadfence();
    __syncthreads();

    // Publish own slice; learn run epoch from the post-increment value.
    unsigned epoch = 0;
    if (t == 0) {
        epoch = atomicAdd(&g_scnt[bh * 16 + blockIdx.y], 1u) + 1u;
        // Wait only the two slices tile 0 needs (usually already done).
        while (atomicAdd(&g_scnt[bh * 16 + 0], 0u) < epoch) __nanosleep(32);
        while (atomicAdd(&g_scnt[bh * 16 + 1], 0u) < epoch) __nanosleep(32);
        __threadfence();
    }
    __syncthreads();

    // ---- Prefetch B tile 0 (overlaps the whole fold) ----
    #pragma unroll
    for (int it = 0; it < 8; it++) {
        const int idx = t + it * 128;
        cp_async16(base_al + OFF_B0 + sw128((uint32_t)idx * 16), kh + (size_t)idx * 8);
    }
    CP_COMMIT();

    // =========================== FOLD PROLOGUE ===========================
    {
        const float* qb = q + boff + (size_t)i0 * DV;
        const float* Wh = W + (size_t)h * DV * DV;
        const float  wd = Wd[h];

        #pragma unroll
        for (int it = 0; it < 32; it++) {
            const int idx = t + it * 128;          // d*64+e
            const int d = idx >> 6, e = idx & 63;
            float val = wd * Wh[idx] + (d == e ? 32.0f : 0.0f);
            __half hi = __float2half(val);
            __half lo = __float2half(val - __half2float(hi));
            const uint32_t off = sw128((uint32_t)(e * 128 + d * 2));
            *reinterpret_cast<__half*>(tilec + OFF_MH + off) = hi;
            *reinterpret_cast<__half*>(tilec + OFF_ML + off) = lo;
        }

        #pragma unroll
        for (int it = 0; it < 4; it++) {
            const int idx = t + it * 128;          // 0..511
            const float4 v0 = reinterpret_cast<const float4*>(qb)[idx * 2];
            const float4 v1 = reinterpret_cast<const float4*>(qb)[idx * 2 + 1];
            __half h0 = __float2half(v0.x), h1 = __float2half(v0.y);
            __half h2 = __float2half(v0.z), h3 = __float2half(v0.w);
            __half h4 = __float2half(v1.x), h5 = __float2half(v1.y);
            __half h6 = __float2half(v1.z), h7 = __float2half(v1.w);
            __half2 hv[4] = { __half2(h0,h1), __half2(h2,h3), __half2(h4,h5), __half2(h6,h7) };
            __half2 lv[4] = {
                __floats2half2_rn(v0.x - __half2float(h0), v0.y - __half2float(h1)),
                __floats2half2_rn(v0.z - __half2float(h2), v0.w - __half2float(h3)),
                __floats2half2_rn(v1.x - __half2float(h4), v1.y - __half2float(h5)),
                __floats2half2_rn(v1.z - __half2float(h6), v1.w - __half2float(h7)) };
            const uint32_t off = sw128((uint32_t)idx * 16);
            *reinterpret_cast<uint4*>(tilec + OFF_QH + off) = *reinterpret_cast<uint4*>(hv);
            *reinterpret_cast<uint4*>(tilec + OFF_QL + off) = *reinterpret_cast<uint4*>(lv);
        }
        __syncthreads();

        const int m0w = (wid & 1) * 32;
        const int n0w = (wid >> 1) * 32;

        float acc[2][4][4];
        #pragma unroll
        for (int m = 0; m < 2; m++)
            #pragma unroll
            for (int n = 0; n < 4; n++)
                #pragma unroll
                for (int r = 0; r < 4; r++) acc[m][n][r] = 0.0f;

        const uint32_t a_row = lane & 15;
        const uint32_t a_ch  = (lane >> 4) << 4;
        const uint32_t b_row = (lane & 7) | ((lane >> 4) << 3);
        const uint32_t b_ch  = ((lane >> 3) & 1) << 4;

        #pragma unroll
        for (int kk = 0; kk < 4; kk++) {
            const uint32_t kb = (uint32_t)kk * 32;
            uint32_t ah[2][4], al[2][4];
            #pragma unroll
            for (int m = 0; m < 2; m++) {
                const uint32_t ro = sw128((uint32_t)(m0w + m * 16 + a_row) * 128 + kb + a_ch);
                ldsm_x4(base_al + OFF_QH + ro, ah[m][0], ah[m][1], ah[m][2], ah[m][3]);
                ldsm_x4(base_al + OFF_QL + ro, al[m][0], al[m][1], al[m][2], al[m][3]);
            }
            uint32_t bh_f[4][2], bl_f[4][2];
            #pragma unroll
            for (int tn = 0; tn < 2; tn++) {
                const uint32_t ro = sw128((uint32_t)(n0w + tn * 16 + b_row) * 128 + kb + b_ch);
                ldsm_x4(base_al + OFF_MH + ro, bh_f[2*tn][0], bh_f[2*tn][1], bh_f[2*tn+1][0], bh_f[2*tn+1][1]);
                ldsm_x4(base_al + OFF_ML + ro, bl_f[2*tn][0], bl_f[2*tn][1], bl_f[2*tn+1][0], bl_f[2*tn+1][1]);
            }
            #pragma unroll
            for (int m = 0; m < 2; m++)
                #pragma unroll
                for (int n = 0; n < 4; n++) {
                    mma_f16(acc[m][n], ah[m], bh_f[n][0], bh_f[n][1]);
                    mma_f16(acc[m][n], ah[m], bl_f[n][0], bl_f[n][1]);
                    mma_f16(acc[m][n], al[m], bh_f[n][0], bh_f[n][1]);
                }
        }
        __syncthreads();   // all Q/M reads done before A overlays Mh

        #pragma unroll
        for (int m = 0; m < 2; m++) {
            #pragma unroll
            for (int half = 0; half < 2; half++) {
                const int row = m0w + m * 16 + half * 8 + (lane >> 2);
                #pragma unroll
                for (int n = 0; n < 4; n++) {
                    const int col = n0w + n * 8 + (lane & 3) * 2;
                    __half2 v = __floats2half2_rn(acc[m][n][half * 2], acc[m][n][half * 2 + 1]);
                    const uint32_t off = sw128((uint32_t)(row * 128 + col * 2));
                    *reinterpret_cast<__half2*>(tilec + OFF_A + off) = v;
                }
            }
        }
    }

    // Wait slices for tile 1 (prefetched at top of jt=0), B0 completion, A tile.
    if (t == 0) {
        while (atomicAdd(&g_scnt[bh * 16 + 2], 0u) < epoch) __nanosleep(32);
        while (atomicAdd(&g_scnt[bh * 16 + 3], 0u) < epoch) __nanosleep(32);
        __threadfence();
    }
    CP_WAIT0();
    __syncthreads();

    // ============================ J-LOOP ============================
    const int m0wj = (wid & 1) * 32;
    const int n0wj = (wid >> 1) * 64;

    const uint32_t a_row = lane & 15;
    const uint32_t a_ch  = (lane >> 4) << 4;
    const uint32_t b_row = (lane & 7) | ((lane >> 4) << 3);
    const uint32_t b_ch  = ((lane >> 3) & 1) << 4;

    const float cbias = Wd[h] * b[h];
    float* obase = out + (size_t)bh * SV * SV;

    const int l3   = lane & 3;
    const int sel  = l3 & 1;            // 0: assemble even fragment, 1: odd
    const int coff = (l3 >> 1) * 4;     // 0 or 4 within the 8-col fragment

    for (int jt = 0; jt < 8; jt++) {
        const uint32_t Bb = base_al + ((jt & 1) ? OFF_B1 : OFF_B0);

        // prefetch next B tile into the other buffer (slices already verified)
        if (jt < 7) {
            const __half* kn = kh + (size_t)(jt + 1) * 128 * DV;
            const uint32_t Bn = base_al + ((jt & 1) ? OFF_B0 : OFF_B1);
            #pragma unroll
            for (int it = 0; it < 8; it++) {
                const int idx = t + it * 128;
                cp_async16(Bn + sw128((uint32_t)idx * 16), kn + (size_t)idx * 8);
            }
            CP_COMMIT();
        }

        // ---- compute 64x128 tile (warp tile 32x64) ----
        float acc[2][8][4];
        #pragma unroll
        for (int m = 0; m < 2; m++)
            #pragma unroll
            for (int n = 0; n < 8; n++)
                #pragma unroll
                for (int r = 0; r < 4; r++) acc[m][n][r] = 0.0f;

        #pragma unroll
        for (int kk = 0; kk < 4; kk++) {
            const uint32_t kb = (uint32_t)kk * 32;
            uint32_t a[2][4];
            #pragma unroll
            for (int m = 0; m < 2; m++) {
                const uint32_t ro = sw128((uint32_t)(m0wj + m * 16 + a_row) * 128 + kb + a_ch);
                ldsm_x4(base_al + OFF_A + ro, a[m][0], a[m][1], a[m][2], a[m][3]);
            }
            uint32_t bf[8][2];
            #pragma unroll
            for (int tn = 0; tn < 4; tn++) {
                const uint32_t ro = sw128((uint32_t)(n0wj + tn * 16 + b_row) * 128 + kb + b_ch);
                ldsm_x4(Bb + ro, bf[2*tn][0], bf[2*tn][1], bf[2*tn+1][0], bf[2*tn+1][1]);
            }
            #pragma unroll
            for (int m = 0; m < 2; m++)
                #pragma unroll
                for (int n = 0; n < 8; n++)
                    mma_f16(acc[m][n], a[m], bf[n][0], bf[n][1]);
        }

        // ---- shuffle-widened streaming-store epilogue (STG.128) ----
        #pragma unroll
        for (int m = 0; m < 2; m++) {
            #pragma unroll
            for (int half = 0; half < 2; half++) {
                const int r = i0 + m0wj + m * 16 + half * 8 + (lane >> 2);
                float* prow = obase + (size_t)r * SV + jt * 128 + n0wj;
                #pragma unroll
                for (int i2 = 0; i2 < 4; i2++) {
                    const float e0 = acc[m][2*i2][half*2+0] + cbias;
                    const float e1 = acc[m][2*i2][half*2+1] + cbias;
                    const float o0 = acc[m][2*i2+1][half*2+0] + cbias;
                    const float o1 = acc[m][2*i2+1][half*2+1] + cbias;
                    const float cx = sel ? e0 : o0;
                    const float cy = sel ? e1 : o1;
                    const float ax = sel ? o0 : e0;
                    const float ay = sel ? o1 : e1;
                    const float rx = __shfl_xor_sync(0xffffffffu, cx, 1);
                    const float ry = __shfl_xor_sync(0xffffffffu, cy, 1);
                    const float v0 = sel ? rx : ax;
                    const float v1 = sel ? ry : ay;
                    const float v2 = sel ? ax : rx;
                    const float v3 = sel ? ay : ry;
                    asm volatile("st.global.cs.v4.f32 [%0], {%1,%2,%3,%4};"
                                 :: "l"(prow + i2 * 16 + sel * 8 + coff),
                                    "f"(v0), "f"(v1), "f"(v2), "f"(v3) : "memory");
                }
            }
        }

        if (jt < 7) {
            // verify slices for the tile prefetched NEXT iteration (jt+2)
            if (t == 0 && jt <= 5) {
                while (atomicAdd(&g_scnt[bh * 16 + 2 * (jt + 2)], 0u) < epoch) __nanosleep(32);
                while (atomicAdd(&g_scnt[bh * 16 + 2 * (jt + 2) + 1], 0u) < epoch) __nanosleep(32);
                __threadfence();
            }
            CP_WAIT0();
            __syncthreads();
        }
    }
}

// ---------------------------------------------------------------------------
extern "C" void kernel_launch(void* const* d_in, const int* in_sizes, int n_in,
                              void* d_out, int out_size)
{
    const float* q  = (const float*)d_in[0];
    const float* k  = (const float*)d_in[1];
    const float* W  = (const float*)d_in[2];
    const float* b  = (const float*)d_in[3];
    const float* Wd = (const float*)d_in[4];
    float* out = (float*)d_out;

    cudaFuncSetAttribute(score_mma_kernel,
                         cudaFuncAttributeMaxDynamicSharedMemorySize, SC_SMEM);

    dim3 g3(1, SV / 64, BH);
    score_mma_kernel<<<g3, 128, SC_SMEM>>>(q, k, W, b, Wd, out);
}

// round 16
// speedup vs baseline: 1.1933x; 1.1933x over previous
#include <cuda_runtime.h>
#include <cuda_fp16.h>
#include <cstdint>
#include <cstddef>

// Problem constants
#define BV 4
#define HN 16
#define SV 1024
#define DV 64
#define BH (BV*HN)

// fp16 k operand (device scratch; no allocation)
__device__ __half g_khi[(size_t)BH * SV * DV];
// per-slice epoch counters: g_scnt[bh*16+y] incremented exactly once per
// launch by CTA (bh,y) -> post-increment value == run epoch (replay-safe).
__device__ unsigned g_scnt[BH * 16];

__device__ __forceinline__ uint32_t smem_u32(const void* p) {
    uint32_t a;
    asm("{ .reg .u64 t; cvta.to.shared.u64 t, %1; cvt.u32.u64 %0, t; }" : "=r"(a) : "l"(p));
    return a;
}
__device__ __forceinline__ uint32_t sw128(uint32_t off) {
    return off ^ ((off >> 3) & 0x70);
}
__device__ __forceinline__ void ldsm_x4(uint32_t addr, uint32_t& r0, uint32_t& r1,
                                        uint32_t& r2, uint32_t& r3) {
    asm volatile("ldmatrix.sync.aligned.m8n8.x4.shared.b16 {%0,%1,%2,%3}, [%4];"
                 : "=r"(r0), "=r"(r1), "=r"(r2), "=r"(r3) : "r"(addr));
}
__device__ __forceinline__ void mma_f16(float* c, const uint32_t* a,
                                        uint32_t b0, uint32_t b1) {
    asm volatile(
        "mma.sync.aligned.m16n8k16.row.col.f32.f16.f16.f32 "
        "{%0,%1,%2,%3}, {%4,%5,%6,%7}, {%8,%9}, {%0,%1,%2,%3};"
        : "+f"(c[0]), "+f"(c[1]), "+f"(c[2]), "+f"(c[3])
        : "r"(a[0]), "r"(a[1]), "r"(a[2]), "r"(a[3]), "r"(b0), "r"(b1));
}
__device__ __forceinline__ void cp_async16(uint32_t smem_dst, const void* gsrc) {
    asm volatile("cp.async.cg.shared.global [%0], [%1], 16;"
                 :: "r"(smem_dst), "l"(gsrc));
}
#define CP_COMMIT() asm volatile("cp.async.commit_group;" ::: "memory")
#define CP_WAIT0()  asm volatile("cp.async.wait_group 0;"  ::: "memory")

__device__ __forceinline__ void wait_flag(const unsigned* p, unsigned epoch) {
    unsigned v;
    while (true) {
        asm volatile("ld.acquire.gpu.b32 %0, [%1];" : "=r"(v) : "l"(p) : "memory");
        if (v >= epoch) break;
        __nanosleep(32);
    }
}

// ---------------------------------------------------------------------------
// Single fused kernel: k-slice convert + release publish + fold prologue
// (overlaps peer conversion) + rotated persistent 64-row strip GEMM.
// grid (1, 16, 64) = 1024 CTAs, 128 threads, 4 CTAs/SM.
// SMEM overlays (from 1K-aligned base, 48K total):
//   fold:   Qh[0,8K) Ql[8K,16K) Mh[16K,24K) Ml[24K,32K)  B0[32K,48K)
//   j-loop: B1[0,16K)           A [16K,24K) (overlays Mh) B0[32K,48K)
// ---------------------------------------------------------------------------
#define OFF_QH 0
#define OFF_QL 8192
#define OFF_MH 16384
#define OFF_ML 24576
#define OFF_A  16384
#define OFF_B0 32768
#define OFF_B1 0
#define SC_SMEM (49152 + 1024)

__global__ __launch_bounds__(128, 4)
void score_mma_kernel(const float* __restrict__ q,
                      const float* __restrict__ kf,
                      const float* __restrict__ W,
                      const float* __restrict__ b,
                      const float* __restrict__ Wd,
                      float* __restrict__ out)
{
    extern __shared__ char smem_raw[];
    const uint32_t smem_base = smem_u32(smem_raw);
    const uint32_t base_al   = (smem_base + 1023u) & ~1023u;
    char* tilec = smem_raw + (base_al - smem_base);

    const int t    = threadIdx.x;
    const int wid  = t >> 5;
    const int lane = t & 31;
    const int bh   = blockIdx.z;
    const int h    = bh % HN;
    const int yidx = blockIdx.y;
    const int i0   = yidx * 64;
    const int start = yidx >> 1;           // rotated start tile (own pair)

    const size_t boff = (size_t)bh * SV * DV;
    const __half* kh = g_khi + boff;
    unsigned* flags = &g_scnt[bh * 16];

    // ================= K-SLICE CONVERT (own 64 rows) =================
    {
        const float* ks = kf + boff + (size_t)i0 * DV;
        __half2* kd = reinterpret_cast<__half2*>(g_khi + boff + (size_t)i0 * DV);
        #pragma unroll
        for (int it = 0; it < 8; it++) {
            const int idx = t + it * 128;
            float4 v = reinterpret_cast<const float4*>(ks)[idx];
            kd[2 * idx]     = __floats2half2_rn(v.x, v.y);
            kd[2 * idx + 1] = __floats2half2_rn(v.z, v.w);
        }
    }
    __syncthreads();
    unsigned epoch = 0;
    if (t == 0) {
        unsigned old;
        asm volatile("atom.release.gpu.add.u32 %0, [%1], %2;"
                     : "=r"(old) : "l"(flags + yidx), "r"(1u) : "memory");
        epoch = old + 1u;
    }

    // =========================== FOLD PROLOGUE ===========================
    // (independent of k -> overlaps peer CTAs' conversions)
    {
        const float* qb = q + boff + (size_t)i0 * DV;
        const float* Wh = W + (size_t)h * DV * DV;
        const float  wd = Wd[h];

        #pragma unroll
        for (int it = 0; it < 32; it++) {
            const int idx = t + it * 128;          // d*64+e
            const int d = idx >> 6, e = idx & 63;
            float val = wd * Wh[idx] + (d == e ? 32.0f : 0.0f);
            __half hi = __float2half(val);
            __half lo = __float2half(val - __half2float(hi));
            const uint32_t off = sw128((uint32_t)(e * 128 + d * 2));
            *reinterpret_cast<__half*>(tilec + OFF_MH + off) = hi;
            *reinterpret_cast<__half*>(tilec + OFF_ML + off) = lo;
        }

        #pragma unroll
        for (int it = 0; it < 4; it++) {
            const int idx = t + it * 128;          // 0..511
            const float4 v0 = reinterpret_cast<const float4*>(qb)[idx * 2];
            const float4 v1 = reinterpret_cast<const float4*>(qb)[idx * 2 + 1];
            __half h0 = __float2half(v0.x), h1 = __float2half(v0.y);
            __half h2 = __float2half(v0.z), h3 = __float2half(v0.w);
            __half h4 = __float2half(v1.x), h5 = __float2half(v1.y);
            __half h6 = __float2half(v1.z), h7 = __float2half(v1.w);
            __half2 hv[4] = { __half2(h0,h1), __half2(h2,h3), __half2(h4,h5), __half2(h6,h7) };
            __half2 lv[4] = {
                __floats2half2_rn(v0.x - __half2float(h0), v0.y - __half2float(h1)),
                __floats2half2_rn(v0.z - __half2float(h2), v0.w - __half2float(h3)),
                __floats2half2_rn(v1.x - __half2float(h4), v1.y - __half2float(h5)),
                __floats2half2_rn(v1.z - __half2float(h6), v1.w - __half2float(h7)) };
            const uint32_t off = sw128((uint32_t)idx * 16);
            *reinterpret_cast<uint4*>(tilec + OFF_QH + off) = *reinterpret_cast<uint4*>(hv);
            *reinterpret_cast<uint4*>(tilec + OFF_QL + off) = *reinterpret_cast<uint4*>(lv);
        }
        __syncthreads();

        const int m0w = (wid & 1) * 32;
        const int n0w = (wid >> 1) * 32;

        float acc[2][4][4];
        #pragma unroll
        for (int m = 0; m < 2; m++)
            #pragma unroll
            for (int n = 0; n < 4; n++)
                #pragma unroll
                for (int r = 0; r < 4; r++) acc[m][n][r] = 0.0f;

        const uint32_t a_row = lane & 15;
        const uint32_t a_ch  = (lane >> 4) << 4;
        const uint32_t b_row = (lane & 7) | ((lane >> 4) << 3);
        const uint32_t b_ch  = ((lane >> 3) & 1) << 4;

        #pragma unroll
        for (int kk = 0; kk < 4; kk++) {
            const uint32_t kb = (uint32_t)kk * 32;
            uint32_t ah[2][4], al[2][4];
            #pragma unroll
            for (int m = 0; m < 2; m++) {
                const uint32_t ro = sw128((uint32_t)(m0w + m * 16 + a_row) * 128 + kb + a_ch);
                ldsm_x4(base_al + OFF_QH + ro, ah[m][0], ah[m][1], ah[m][2], ah[m][3]);
                ldsm_x4(base_al + OFF_QL + ro, al[m][0], al[m][1], al[m][2], al[m][3]);
            }
            uint32_t bh_f[4][2], bl_f[4][2];
            #pragma unroll
            for (int tn = 0; tn < 2; tn++) {
                const uint32_t ro = sw128((uint32_t)(n0w + tn * 16 + b_row) * 128 + kb + b_ch);
                ldsm_x4(base_al + OFF_MH + ro, bh_f[2*tn][0], bh_f[2*tn][1], bh_f[2*tn+1][0], bh_f[2*tn+1][1]);
                ldsm_x4(base_al + OFF_ML + ro, bl_f[2*tn][0], bl_f[2*tn][1], bl_f[2*tn+1][0], bl_f[2*tn+1][1]);
            }
            #pragma unroll
            for (int m = 0; m < 2; m++)
                #pragma unroll
                for (int n = 0; n < 4; n++) {
                    mma_f16(acc[m][n], ah[m], bh_f[n][0], bh_f[n][1]);
                    mma_f16(acc[m][n], ah[m], bl_f[n][0], bl_f[n][1]);
                    mma_f16(acc[m][n], al[m], bh_f[n][0], bh_f[n][1]);
                }
        }
        __syncthreads();   // all Q/M reads done before A overlays Mh

        #pragma unroll
        for (int m = 0; m < 2; m++) {
            #pragma unroll
            for (int half = 0; half < 2; half++) {
                const int row = m0w + m * 16 + half * 8 + (lane >> 2);
                #pragma unroll
                for (int n = 0; n < 4; n++) {
                    const int col = n0w + n * 8 + (lane & 3) * 2;
                    __half2 v = __floats2half2_rn(acc[m][n][half * 2], acc[m][n][half * 2 + 1]);
                    const uint32_t off = sw128((uint32_t)(row * 128 + col * 2));
                    *reinterpret_cast<__half2*>(tilec + OFF_A + off) = v;
                }
            }
        }
    }

    // ---- Wait only the slices of the first TWO rotated tiles (own pair +
    //      adjacent pair; launched together -> near-zero wait) ----
    if (t == 0) {
        const int t0s = 2 * start;
        const int t1s = 2 * ((start + 1) & 7);
        wait_flag(flags + t0s,     epoch);
        wait_flag(flags + t0s + 1, epoch);
        wait_flag(flags + t1s,     epoch);
        wait_flag(flags + t1s + 1, epoch);
    }
    __syncthreads();     // A visible; acquired slices visible to all threads

    // ---- Prefetch B tile_eff(0) = start ----
    {
        const __half* k0 = kh + (size_t)start * 128 * DV;
        #pragma unroll
        for (int it = 0; it < 8; it++) {
            const int idx = t + it * 128;
            cp_async16(base_al + OFF_B0 + sw128((uint32_t)idx * 16), k0 + (size_t)idx * 8);
        }
    }
    CP_COMMIT();
    CP_WAIT0();
    __syncthreads();

    // ============================ J-LOOP (rotated) ============================
    const int m0wj = (wid & 1) * 32;
    const int n0wj = (wid >> 1) * 64;

    const uint32_t a_row = lane & 15;
    const uint32_t a_ch  = (lane >> 4) << 4;
    const uint32_t b_row = (lane & 7) | ((lane >> 4) << 3);
    const uint32_t b_ch  = ((lane >> 3) & 1) << 4;

    const float cbias = Wd[h] * b[h];
    float* obase = out + (size_t)bh * SV * SV;

    const int l3   = lane & 3;
    const int sel  = l3 & 1;            // 0: assemble even fragment, 1: odd
    const int coff = (l3 >> 1) * 4;     // 0 or 4 within the 8-col fragment

    for (int jt = 0; jt < 8; jt++) {
        const int cur = (start + jt) & 7;
        const uint32_t Bb = base_al + ((jt & 1) ? OFF_B1 : OFF_B0);

        // prefetch next B tile into the other buffer (flags verified last tail)
        if (jt < 7) {
            const int nxt = (start + jt + 1) & 7;
            const __half* kn = kh + (size_t)nxt * 128 * DV;
            const uint32_t Bn = base_al + ((jt & 1) ? OFF_B0 : OFF_B1);
            #pragma unroll
            for (int it = 0; it < 8; it++) {
                const int idx = t + it * 128;
                cp_async16(Bn + sw128((uint32_t)idx * 16), kn + (size_t)idx * 8);
            }
            CP_COMMIT();
        }

        // ---- compute 64x128 tile (warp tile 32x64) ----
        float acc[2][8][4];
        #pragma unroll
        for (int m = 0; m < 2; m++)
            #pragma unroll
            for (int n = 0; n < 8; n++)
                #pragma unroll
                for (int r = 0; r < 4; r++) acc[m][n][r] = 0.0f;

        #pragma unroll
        for (int kk = 0; kk < 4; kk++) {
            const uint32_t kb = (uint32_t)kk * 32;
            uint32_t a[2][4];
            #pragma unroll
            for (int m = 0; m < 2; m++) {
                const uint32_t ro = sw128((uint32_t)(m0wj + m * 16 + a_row) * 128 + kb + a_ch);
                ldsm_x4(base_al + OFF_A + ro, a[m][0], a[m][1], a[m][2], a[m][3]);
            }
            uint32_t bf[8][2];
            #pragma unroll
            for (int tn = 0; tn < 4; tn++) {
                const uint32_t ro = sw128((uint32_t)(n0wj + tn * 16 + b_row) * 128 + kb + b_ch);
                ldsm_x4(Bb + ro, bf[2*tn][0], bf[2*tn][1], bf[2*tn+1][0], bf[2*tn+1][1]);
            }
            #pragma unroll
            for (int m = 0; m < 2; m++)
                #pragma unroll
                for (int n = 0; n < 8; n++)
                    mma_f16(acc[m][n], a[m], bf[n][0], bf[n][1]);
        }

        // ---- shuffle-widened streaming-store epilogue (STG.128) ----
        #pragma unroll
        for (int m = 0; m < 2; m++) {
            #pragma unroll
            for (int half = 0; half < 2; half++) {
                const int r = i0 + m0wj + m * 16 + half * 8 + (lane >> 2);
                float* prow = obase + (size_t)r * SV + cur * 128 + n0wj;
                #pragma unroll
                for (int i2 = 0; i2 < 4; i2++) {
                    const float e0 = acc[m][2*i2][half*2+0] + cbias;
                    const float e1 = acc[m][2*i2][half*2+1] + cbias;
                    const float o0 = acc[m][2*i2+1][half*2+0] + cbias;
                    const float o1 = acc[m][2*i2+1][half*2+1] + cbias;
                    const float cx = sel ? e0 : o0;
                    const float cy = sel ? e1 : o1;
                    const float ax = sel ? o0 : e0;
                    const float ay = sel ? o1 : e1;
                    const float rx = __shfl_xor_sync(0xffffffffu, cx, 1);
                    const float ry = __shfl_xor_sync(0xffffffffu, cy, 1);
                    const float v0 = sel ? rx : ax;
                    const float v1 = sel ? ry : ay;
                    const float v2 = sel ? ax : rx;
                    const float v3 = sel ? ay : ry;
                    asm volatile("st.global.cs.v4.f32 [%0], {%1,%2,%3,%4};"
                                 :: "l"(prow + i2 * 16 + sel * 8 + coff),
                                    "f"(v0), "f"(v1), "f"(v2), "f"(v3) : "memory");
                }
            }
        }

        if (jt < 7) {
            // verify slices of the tile prefetched NEXT iteration; acquire
            // loads by t0 only, hidden under cp.async completion (no fence)
            if (t == 0 && jt <= 5) {
                const int fs = 2 * ((start + jt + 2) & 7);
                wait_flag(flags + fs,     epoch);
                wait_flag(flags + fs + 1, epoch);
            }
            CP_WAIT0();
            __syncthreads();
        }
    }
}

// ---------------------------------------------------------------------------
extern "C" void kernel_launch(void* const* d_in, const int* in_sizes, int n_in,
                              void* d_out, int out_size)
{
    const float* q  = (const float*)d_in[0];
    const float* k  = (const float*)d_in[1];
    const float* W  = (const float*)d_in[2];
    const float* b  = (const float*)d_in[3];
    const float* Wd = (const float*)d_in[4];
    float* out = (float*)d_out;

    cudaFuncSetAttribute(score_mma_kernel,
                         cudaFuncAttributeMaxDynamicSharedMemorySize, SC_SMEM);

    dim3 g3(1, SV / 64, BH);
    score_mma_kernel<<<g3, 128, SC_SMEM>>>(q, k, W, b, Wd, out);
}

// round 17
// speedup vs baseline: 1.2341x; 1.0342x over previous
#include <cuda_runtime.h>
#include <cuda_fp16.h>
#include <cstdint>
#include <cstddef>

// Problem constants
#define BV 4
#define HN 16
#define SV 1024
#define DV 64
#define BH (BV*HN)

// fp16 k operand (device scratch; no allocation)
__device__ __half g_khi[(size_t)BH * SV * DV];
// monotonic per-bh arrival counters (ticket scheme, graph-replay safe)
__device__ unsigned g_cnt[BH];

__device__ __forceinline__ uint32_t smem_u32(const void* p) {
    uint32_t a;
    asm("{ .reg .u64 t; cvta.to.shared.u64 t, %1; cvt.u32.u64 %0, t; }" : "=r"(a) : "l"(p));
    return a;
}
__device__ __forceinline__ uint32_t sw128(uint32_t off) {
    return off ^ ((off >> 3) & 0x70);
}
__device__ __forceinline__ void ldsm_x4(uint32_t addr, uint32_t& r0, uint32_t& r1,
                                        uint32_t& r2, uint32_t& r3) {
    asm volatile("ldmatrix.sync.aligned.m8n8.x4.shared.b16 {%0,%1,%2,%3}, [%4];"
                 : "=r"(r0), "=r"(r1), "=r"(r2), "=r"(r3) : "r"(addr));
}
__device__ __forceinline__ void mma_f16(float* c, const uint32_t* a,
                                        uint32_t b0, uint32_t b1) {
    asm volatile(
        "mma.sync.aligned.m16n8k16.row.col.f32.f16.f16.f32 "
        "{%0,%1,%2,%3}, {%4,%5,%6,%7}, {%8,%9}, {%0,%1,%2,%3};"
        : "+f"(c[0]), "+f"(c[1]), "+f"(c[2]), "+f"(c[3])
        : "r"(a[0]), "r"(a[1]), "r"(a[2]), "r"(a[3]), "r"(b0), "r"(b1));
}
__device__ __forceinline__ void cp_async16(uint32_t smem_dst, const void* gsrc) {
    asm volatile("cp.async.cg.shared.global [%0], [%1], 16;"
                 :: "r"(smem_dst), "l"(gsrc));
}
#define CP_COMMIT() asm volatile("cp.async.commit_group;" ::: "memory")
#define CP_WAIT0()  asm volatile("cp.async.wait_group 0;"  ::: "memory")
#define BAR_PAIR(id) asm volatile("bar.sync %0, 64;" :: "r"(id) : "memory")

// ---------------------------------------------------------------------------
// Single fused kernel: k-slice convert + ticket barrier + fold prologue +
// persistent 64-row strip GEMM. Pair-decoupled B pipeline: warps {0,1} own
// B cols 0-63, warps {2,3} own cols 64-127; each pair double-buffers its own
// 8KB half and syncs with a 64-thread named barrier (no block-wide sync in
// the j-loop).
// grid (1, 16, 64) = 1024 CTAs, 128 threads, 4 CTAs/SM.
// SMEM overlays (from 1K-aligned base, 48K total):
//   fold:   Qh[0,8K) Ql[8K,16K) Mh[16K,24K) Ml[24K,32K)   [32K,48K) free
//   j-loop: pair1 B{buf0[0,8K), buf1[8K,16K)} | A[16K,24K) (overlays Mh) |
//           pair0 B{buf0[32K,40K), buf1[40K,48K)}
// ---------------------------------------------------------------------------
#define OFF_QH 0
#define OFF_QL 8192
#define OFF_MH 16384
#define OFF_ML 24576
#define OFF_A  16384
#define SC_SMEM (49152 + 1024)

__global__ __launch_bounds__(128, 4)
void score_mma_kernel(const float* __restrict__ q,
                      const float* __restrict__ kf,
                      const float* __restrict__ W,
                      const float* __restrict__ b,
                      const float* __restrict__ Wd,
                      float* __restrict__ out)
{
    extern __shared__ char smem_raw[];
    const uint32_t smem_base = smem_u32(smem_raw);
    const uint32_t base_al   = (smem_base + 1023u) & ~1023u;
    char* tilec = smem_raw + (base_al - smem_base);

    const int t    = threadIdx.x;
    const int wid  = t >> 5;
    const int lane = t & 31;
    const int pair = wid >> 1;          // 0: warps 0-1 (cols 0-63), 1: warps 2-3
    const int tp   = t & 63;            // thread index within pair
    const int bh   = blockIdx.z;
    const int h    = bh % HN;
    const int i0   = blockIdx.y * 64;

    const size_t boff = (size_t)bh * SV * DV;
    const __half* kh = g_khi + boff;

    // per-pair B double buffers
    const uint32_t Bbuf0 = base_al + (pair ? 0u     : 32768u);
    const uint32_t Bbuf1 = base_al + (pair ? 8192u  : 40960u);

    // ================= K-SLICE CONVERT (own 64 rows) =================
    {
        const float* ks = kf + boff + (size_t)i0 * DV;
        __half2* kd = reinterpret_cast<__half2*>(g_khi + boff + (size_t)i0 * DV);
        #pragma unroll
        for (int it = 0; it < 8; it++) {
            const int idx = t + it * 128;
            float4 v = reinterpret_cast<const float4*>(ks)[idx];
            kd[2 * idx]     = __floats2half2_rn(v.x, v.y);
            kd[2 * idx + 1] = __floats2half2_rn(v.z, v.w);
        }
    }
    __threadfence();
    __syncthreads();
    unsigned target = 0;
    if (t == 0) {
        unsigned my = atomicAdd(&g_cnt[bh], 1u);
        target = (my / 16u + 1u) * 16u;
    }

    // =========================== FOLD PROLOGUE ===========================
    {
        const float* qb = q + boff + (size_t)i0 * DV;
        const float* Wh = W + (size_t)h * DV * DV;
        const float  wd = Wd[h];

        #pragma unroll
        for (int it = 0; it < 32; it++) {
            const int idx = t + it * 128;          // d*64+e
            const int d = idx >> 6, e = idx & 63;
            float val = wd * Wh[idx] + (d == e ? 32.0f : 0.0f);
            __half hi = __float2half(val);
            __half lo = __float2half(val - __half2float(hi));
            const uint32_t off = sw128((uint32_t)(e * 128 + d * 2));
            *reinterpret_cast<__half*>(tilec + OFF_MH + off) = hi;
            *reinterpret_cast<__half*>(tilec + OFF_ML + off) = lo;
        }

        #pragma unroll
        for (int it = 0; it < 4; it++) {
            const int idx = t + it * 128;          // 0..511
            const float4 v0 = reinterpret_cast<const float4*>(qb)[idx * 2];
            const float4 v1 = reinterpret_cast<const float4*>(qb)[idx * 2 + 1];
            __half h0 = __float2half(v0.x), h1 = __float2half(v0.y);
            __half h2 = __float2half(v0.z), h3 = __float2half(v0.w);
            __half h4 = __float2half(v1.x), h5 = __float2half(v1.y);
            __half h6 = __float2half(v1.z), h7 = __float2half(v1.w);
            __half2 hv[4] = { __half2(h0,h1), __half2(h2,h3), __half2(h4,h5), __half2(h6,h7) };
            __half2 lv[4] = {
                __floats2half2_rn(v0.x - __half2float(h0), v0.y - __half2float(h1)),
                __floats2half2_rn(v0.z - __half2float(h2), v0.w - __half2float(h3)),
                __floats2half2_rn(v1.x - __half2float(h4), v1.y - __half2float(h5)),
                __floats2half2_rn(v1.z - __half2float(h6), v1.w - __half2float(h7)) };
            const uint32_t off = sw128((uint32_t)idx * 16);
            *reinterpret_cast<uint4*>(tilec + OFF_QH + off) = *reinterpret_cast<uint4*>(hv);
            *reinterpret_cast<uint4*>(tilec + OFF_QL + off) = *reinterpret_cast<uint4*>(lv);
        }
        __syncthreads();

        const int m0w = (wid & 1) * 32;
        const int n0w = (wid >> 1) * 32;

        float acc[2][4][4];
        #pragma unroll
        for (int m = 0; m < 2; m++)
            #pragma unroll
            for (int n = 0; n < 4; n++)
                #pragma unroll
                for (int r = 0; r < 4; r++) acc[m][n][r] = 0.0f;

        const uint32_t a_row = lane & 15;
        const uint32_t a_ch  = (lane >> 4) << 4;
        const uint32_t b_row = (lane & 7) | ((lane >> 4) << 3);
        const uint32_t b_ch  = ((lane >> 3) & 1) << 4;

        #pragma unroll
        for (int kk = 0; kk < 4; kk++) {
            const uint32_t kb = (uint32_t)kk * 32;
            uint32_t ah[2][4], al[2][4];
            #pragma unroll
            for (int m = 0; m < 2; m++) {
                const uint32_t ro = sw128((uint32_t)(m0w + m * 16 + a_row) * 128 + kb + a_ch);
                ldsm_x4(base_al + OFF_QH + ro, ah[m][0], ah[m][1], ah[m][2], ah[m][3]);
                ldsm_x4(base_al + OFF_QL + ro, al[m][0], al[m][1], al[m][2], al[m][3]);
            }
            uint32_t bh_f[4][2], bl_f[4][2];
            #pragma unroll
            for (int tn = 0; tn < 2; tn++) {
                const uint32_t ro = sw128((uint32_t)(n0w + tn * 16 + b_row) * 128 + kb + b_ch);
                ldsm_x4(base_al + OFF_MH + ro, bh_f[2*tn][0], bh_f[2*tn][1], bh_f[2*tn+1][0], bh_f[2*tn+1][1]);
                ldsm_x4(base_al + OFF_ML + ro, bl_f[2*tn][0], bl_f[2*tn][1], bl_f[2*tn+1][0], bl_f[2*tn+1][1]);
            }
            #pragma unroll
            for (int m = 0; m < 2; m++)
                #pragma unroll
                for (int n = 0; n < 4; n++) {
                    mma_f16(acc[m][n], ah[m], bh_f[n][0], bh_f[n][1]);
                    mma_f16(acc[m][n], ah[m], bl_f[n][0], bl_f[n][1]);
                    mma_f16(acc[m][n], al[m], bh_f[n][0], bh_f[n][1]);
                }
        }
        __syncthreads();   // all Q/M reads done before A / pair-1 buffers overlay

        #pragma unroll
        for (int m = 0; m < 2; m++) {
            #pragma unroll
            for (int half = 0; half < 2; half++) {
                const int row = m0w + m * 16 + half * 8 + (lane >> 2);
                #pragma unroll
                for (int n = 0; n < 4; n++) {
                    const int col = n0w + n * 8 + (lane & 3) * 2;
                    __half2 v = __floats2half2_rn(acc[m][n][half * 2], acc[m][n][half * 2 + 1]);
                    const uint32_t off = sw128((uint32_t)(row * 128 + col * 2));
                    *reinterpret_cast<__half2*>(tilec + OFF_A + off) = v;
                }
            }
        }
    }

    // ================= TICKET BARRIER: wait for all 16 peers =================
    if (t == 0) {
        while (atomicAdd(&g_cnt[bh], 0u) < target) __nanosleep(64);
        __threadfence();
    }
    __syncthreads();     // A visible to all; peers' k conversions visible

    // ---- Prefetch B tile 0: each pair loads ITS OWN 64x128B half ----
    {
        const __half* k0 = kh + (size_t)pair * 64 * DV;
        #pragma unroll
        for (int it = 0; it < 8; it++) {
            const int idx = tp + it * 64;          // 0..511 chunks of pair half
            cp_async16(Bbuf0 + sw128((uint32_t)idx * 16), k0 + (size_t)idx * 8);
        }
    }
    CP_COMMIT();
    CP_WAIT0();
    __syncthreads();     // one last block-wide sync; pairs decouple from here

    // ============================ J-LOOP (pair-decoupled) ============================
    const int m0wj = (wid & 1) * 32;
    const int n0wj = pair * 64;          // global col base of this pair's half

    const uint32_t a_row = lane & 15;
    const uint32_t a_ch  = (lane >> 4) << 4;
    const uint32_t b_row = (lane & 7) | ((lane >> 4) << 3);
    const uint32_t b_ch  = ((lane >> 3) & 1) << 4;

    const float cbias = Wd[h] * b[h];
    float* obase = out + (size_t)bh * SV * SV;

    const int l3   = lane & 3;
    const int sel  = l3 & 1;            // 0: assemble even fragment, 1: odd
    const int coff = (l3 >> 1) * 4;     // 0 or 4 within the 8-col fragment

    for (int jt = 0; jt < 8; jt++) {
        const uint32_t Bb = (jt & 1) ? Bbuf1 : Bbuf0;

        // prefetch own half of next B tile into the other pair-buffer
        if (jt < 7) {
            const __half* kn = kh + (size_t)((jt + 1) * 128 + pair * 64) * DV;
            const uint32_t Bn = (jt & 1) ? Bbuf0 : Bbuf1;
            #pragma unroll
            for (int it = 0; it < 8; it++) {
                const int idx = tp + it * 64;
                cp_async16(Bn + sw128((uint32_t)idx * 16), kn + (size_t)idx * 8);
            }
            CP_COMMIT();
        }

        // ---- compute 64x64 pair slab (warp tile 32x64; B rows local 0-63) ----
        float acc[2][8][4];
        #pragma unroll
        for (int m = 0; m < 2; m++)
            #pragma unroll
            for (int n = 0; n < 8; n++)
                #pragma unroll
                for (int r = 0; r < 4; r++) acc[m][n][r] = 0.0f;

        #pragma unroll
        for (int kk = 0; kk < 4; kk++) {
            const uint32_t kb = (uint32_t)kk * 32;
            uint32_t a[2][4];
            #pragma unroll
            for (int m = 0; m < 2; m++) {
                const uint32_t ro = sw128((uint32_t)(m0wj + m * 16 + a_row) * 128 + kb + a_ch);
                ldsm_x4(base_al + OFF_A + ro, a[m][0], a[m][1], a[m][2], a[m][3]);
            }
            uint32_t bf[8][2];
            #pragma unroll
            for (int tn = 0; tn < 4; tn++) {
                const uint32_t ro = sw128((uint32_t)(tn * 16 + b_row) * 128 + kb + b_ch);
                ldsm_x4(Bb + ro, bf[2*tn][0], bf[2*tn][1], bf[2*tn+1][0], bf[2*tn+1][1]);
            }
            #pragma unroll
            for (int m = 0; m < 2; m++)
                #pragma unroll
                for (int n = 0; n < 8; n++)
                    mma_f16(acc[m][n], a[m], bf[n][0], bf[n][1]);
        }

        // ---- shuffle-widened streaming-store epilogue (STG.128) ----
        #pragma unroll
        for (int m = 0; m < 2; m++) {
            #pragma unroll
            for (int half = 0; half < 2; half++) {
                const int r = i0 + m0wj + m * 16 + half * 8 + (lane >> 2);
                float* prow = obase + (size_t)r * SV + jt * 128 + n0wj;
                #pragma unroll
                for (int i2 = 0; i2 < 4; i2++) {
                    const float e0 = acc[m][2*i2][half*2+0] + cbias;
                    const float e1 = acc[m][2*i2][half*2+1] + cbias;
                    const float o0 = acc[m][2*i2+1][half*2+0] + cbias;
                    const float o1 = acc[m][2*i2+1][half*2+1] + cbias;
                    const float cx = sel ? e0 : o0;
                    const float cy = sel ? e1 : o1;
                    const float ax = sel ? o0 : e0;
                    const float ay = sel ? o1 : e1;
                    const float rx = __shfl_xor_sync(0xffffffffu, cx, 1);
                    const float ry = __shfl_xor_sync(0xffffffffu, cy, 1);
                    const float v0 = sel ? rx : ax;
                    const float v1 = sel ? ry : ay;
                    const float v2 = sel ? ax : rx;
                    const float v3 = sel ? ay : ry;
                    asm volatile("st.global.cs.v4.f32 [%0], {%1,%2,%3,%4};"
                                 :: "l"(prow + i2 * 16 + sel * 8 + coff),
                                    "f"(v0), "f"(v1), "f"(v2), "f"(v3) : "memory");
                }
            }
        }

        if (jt < 7) {
            CP_WAIT0();
            BAR_PAIR(pair + 1);   // 64-thread pair barrier: partner's chunks visible
        }
    }
}

// ---------------------------------------------------------------------------
extern "C" void kernel_launch(void* const* d_in, const int* in_sizes, int n_in,
                              void* d_out, int out_size)
{
    const float* q  = (const float*)d_in[0];
    const float* k  = (const float*)d_in[1];
    const float* W  = (const float*)d_in[2];
    const float* b  = (const float*)d_in[3];
    const float* Wd = (const float*)d_in[4];
    float* out = (float*)d_out;

    cudaFuncSetAttribute(score_mma_kernel,
                         cudaFuncAttributeMaxDynamicSharedMemorySize, SC_SMEM);

    dim3 g3(1, SV / 64, BH);
    score_mma_kernel<<<g3, 128, SC_SMEM>>>(q, k, W, b, Wd, out);
}